// round 13
// baseline (speedup 1.0000x reference)
#include <cuda_runtime.h>
#include <cuda_fp16.h>
#include <cstdint>

// ============================================================================
// Longformer attention, all-fp16 tensor-core path.
//   Projections: fp16x2 GEMM (A fp16, W split fp16 hi/lo, 2 products)
//   Attention:   single-fp16 flash attention on mma.sync (fp32 accum/softmax)
// ============================================================================

constexpr int D_MODEL = 1024;
constexpr int S_LEN   = 2048;
constexpr int BATCH   = 2;
constexpr int NHEADS  = 16;
constexpr int DHEAD   = 64;
constexpr int M_TOK   = BATCH * S_LEN;   // 4096
constexpr int WIN     = 256;

// scratch (device globals: no allocation allowed)
__device__ __half g_xh[M_TOK * D_MODEL];                 // x as fp16
__device__ __half g_wh[4 * D_MODEL * D_MODEL];           // W hi [K,N] fp16
__device__ __half g_wl[4 * D_MODEL * D_MODEL];           // W lo [K,N] fp16
__device__ __half g_q[BATCH * NHEADS * S_LEN * DHEAD];   // [bh][s][d]
__device__ __half g_k[BATCH * NHEADS * DHEAD * S_LEN];   // [bh][d][s] (transposed)
__device__ __half g_v[BATCH * NHEADS * S_LEN * DHEAD];   // [bh][s][d]
__device__ __half g_att[M_TOK * D_MODEL];                // attention out fp16

// ----------------------------------------------------------------------------
// helpers
// ----------------------------------------------------------------------------
__device__ __forceinline__ uint32_t smem_u32(const void* p) {
    return (uint32_t)__cvta_generic_to_shared(p);
}
__device__ __forceinline__ void ldsm_x4(uint32_t (&r)[4], uint32_t addr) {
    asm volatile("ldmatrix.sync.aligned.m8n8.x4.shared.b16 {%0,%1,%2,%3}, [%4];"
                 : "=r"(r[0]), "=r"(r[1]), "=r"(r[2]), "=r"(r[3]) : "r"(addr));
}
__device__ __forceinline__ void ldsm_x4_t(uint32_t (&r)[4], uint32_t addr) {
    asm volatile("ldmatrix.sync.aligned.m8n8.x4.trans.shared.b16 {%0,%1,%2,%3}, [%4];"
                 : "=r"(r[0]), "=r"(r[1]), "=r"(r[2]), "=r"(r[3]) : "r"(addr));
}
__device__ __forceinline__ void mma16816h(float (&d)[4], const uint32_t (&a)[4],
                                          uint32_t b0, uint32_t b1) {
    asm volatile("mma.sync.aligned.m16n8k16.row.col.f32.f16.f16.f32 "
                 "{%0,%1,%2,%3}, {%4,%5,%6,%7}, {%8,%9}, {%0,%1,%2,%3};"
                 : "+f"(d[0]), "+f"(d[1]), "+f"(d[2]), "+f"(d[3])
                 : "r"(a[0]), "r"(a[1]), "r"(a[2]), "r"(a[3]), "r"(b0), "r"(b1));
}
__device__ __forceinline__ uint32_t pack2h(__half a, __half b) {
    uint16_t x = *(uint16_t*)&a, y = *(uint16_t*)&b;
    return (uint32_t)x | ((uint32_t)y << 16);
}

// ----------------------------------------------------------------------------
// x: fp32 -> fp16
// ----------------------------------------------------------------------------
__global__ void splitx_kernel(const float* __restrict__ s, __half* __restrict__ h, int n)
{
    const int i = (blockIdx.x * blockDim.x + threadIdx.x) * 4;
    if (i >= n) return;
    float4 v = *(const float4*)(s + i);
    __align__(8) __half hh[4] = { __float2half(v.x), __float2half(v.y),
                                  __float2half(v.z), __float2half(v.w) };
    *(uint2*)&h[i] = *(uint2*)hh;
}

// ----------------------------------------------------------------------------
// W: fp32 -> fp16 hi + fp16 lo residual. All 4 weights in one launch (grid.y).
// ----------------------------------------------------------------------------
__global__ void splitw_kernel(const float* __restrict__ W0, const float* __restrict__ W1,
                              const float* __restrict__ W2, const float* __restrict__ W3,
                              __half* __restrict__ h, __half* __restrict__ l)
{
    constexpr int NW = D_MODEL * D_MODEL;
    const int wsel = blockIdx.y;
    const float* W = (wsel == 0) ? W0 : (wsel == 1) ? W1 : (wsel == 2) ? W2 : W3;
    const int i = (blockIdx.x * blockDim.x + threadIdx.x) * 4;
    if (i >= NW) return;
    float4 v = *(const float4*)(W + i);
    float a[4] = { v.x, v.y, v.z, v.w };
    __align__(8) __half hh[4], ll[4];
#pragma unroll
    for (int j = 0; j < 4; ++j) {
        hh[j] = __float2half(a[j]);
        ll[j] = __float2half(a[j] - __half2float(hh[j]));
    }
    const size_t o = (size_t)wsel * NW + i;
    *(uint2*)&h[o] = *(uint2*)hh;
    *(uint2*)&l[o] = *(uint2*)ll;
}

// ----------------------------------------------------------------------------
// fp16x2 GEMM: C[4096,1024] = A_fp16 * (Wh + Wl) + bias,  W = [K,N]
// 128x128 tile, KSTEP 16, 256 thr = 8 warps (4m x 2n), warp 32x64. 2 products.
// MODE 0: fp32 row-major [M,N]        (final projection -> d_out)
// MODE 1: fp16 split-head [bh][s][d]  (Q, V)
// MODE 2: fp16 transposed [bh][d][s]  (K)
// ----------------------------------------------------------------------------
template<int MODE>
__global__ __launch_bounds__(256, 2)
void gemm_fp16x2(const __half* __restrict__ A,
                 const __half* __restrict__ Bh, const __half* __restrict__ Bl,
                 const float* __restrict__ bias,
                 float* __restrict__ Cf, __half* __restrict__ Ch)
{
    constexpr int K   = D_MODEL;
    constexpr int N   = D_MODEL;
    constexpr int LDA = 24;    // 16 + 8 pad
    constexpr int LDB = 136;   // 128 + 8 pad

    __shared__ __half As[2][128 * LDA];
    __shared__ __half Bs[2][2][16 * LDB];   // [buf][hi/lo]

    const int tid  = threadIdx.x;
    const int lane = tid & 31;
    const int w    = tid >> 5;
    const int wm   = w >> 1;
    const int wn   = w & 1;
    const int bm   = blockIdx.y * 128;
    const int bn   = blockIdx.x * 128;

    const int arow = tid >> 1, acol = (tid & 1) * 8;
    const int brow = tid >> 4, bcol = (tid & 15) * 8;
    const __half* Ap  = A  + (size_t)(bm + arow) * K + acol;
    const __half* Bph = Bh + (size_t)brow * N + bn + bcol;
    const __half* Bpl = Bl + (size_t)brow * N + bn + bcol;
    const int a_soff = arow * LDA + acol;
    const int b_soff = brow * LDB + bcol;

    const int lr = lane & 15, lc = lane >> 4;
    uint32_t aAddr[2][2];      // [buf][mt]
    uint32_t bAddr[2][2][4];   // [buf][part][nt]
#pragma unroll
    for (int b2 = 0; b2 < 2; ++b2) {
        uint32_t ab = smem_u32(&As[b2][0]);
#pragma unroll
        for (int mt = 0; mt < 2; ++mt)
            aAddr[b2][mt] = ab + ((wm * 32 + mt * 16 + lr) * LDA + lc * 8) * 2;
#pragma unroll
        for (int p = 0; p < 2; ++p) {
            uint32_t bb = smem_u32(&Bs[b2][p][0]);
#pragma unroll
            for (int nt = 0; nt < 4; ++nt)
                bAddr[b2][p][nt] = bb + (lr * LDB + wn * 64 + nt * 16 + lc * 8) * 2;
        }
    }

    float c[2][8][4];
#pragma unroll
    for (int mt = 0; mt < 2; ++mt)
#pragma unroll
        for (int cn = 0; cn < 8; ++cn)
#pragma unroll
            for (int e = 0; e < 4; ++e) c[mt][cn][e] = 0.f;

    *(uint4*)&As[0][a_soff]    = *(const uint4*)Ap;
    *(uint4*)&Bs[0][0][b_soff] = *(const uint4*)Bph;
    *(uint4*)&Bs[0][1][b_soff] = *(const uint4*)Bpl;
    __syncthreads();

    int buf = 0;
    for (int t = 0; t < K / 16; ++t) {
        uint4 ra, rbh, rbl;
        const bool pf = (t + 1) < K / 16;
        if (pf) {
            ra  = *(const uint4*)(Ap + (t + 1) * 16);
            rbh = *(const uint4*)(Bph + (size_t)(t + 1) * 16 * N);
            rbl = *(const uint4*)(Bpl + (size_t)(t + 1) * 16 * N);
        }

        uint32_t a_f[2][4];
#pragma unroll
        for (int mt = 0; mt < 2; ++mt) ldsm_x4(a_f[mt], aAddr[buf][mt]);
#pragma unroll
        for (int nt = 0; nt < 4; ++nt) {
            uint32_t b_h[4], b_l[4];
            ldsm_x4_t(b_h, bAddr[buf][0][nt]);
            ldsm_x4_t(b_l, bAddr[buf][1][nt]);
#pragma unroll
            for (int hh = 0; hh < 2; ++hh) {
                const int cn = nt * 2 + hh;
#pragma unroll
                for (int mt = 0; mt < 2; ++mt) {
                    mma16816h(c[mt][cn], a_f[mt], b_h[2 * hh], b_h[2 * hh + 1]);
                    mma16816h(c[mt][cn], a_f[mt], b_l[2 * hh], b_l[2 * hh + 1]);
                }
            }
        }

        if (pf) {
            const int nb = buf ^ 1;
            *(uint4*)&As[nb][a_soff]    = ra;
            *(uint4*)&Bs[nb][0][b_soff] = rbh;
            *(uint4*)&Bs[nb][1][b_soff] = rbl;
        }
        __syncthreads();
        buf ^= 1;
    }

    // epilogue
    const int r_base = bm + wm * 32 + (lane >> 2);
    const int c_base = bn + wn * 64 + (lane & 3) * 2;
#pragma unroll
    for (int mt = 0; mt < 2; ++mt) {
#pragma unroll
        for (int cn = 0; cn < 8; ++cn) {
            const int r0 = r_base + mt * 16;
            const int c0 = c_base + cn * 8;
            const float b0 = bias[c0], b1 = bias[c0 + 1];
            const float v00 = c[mt][cn][0] + b0, v01 = c[mt][cn][1] + b1;  // row r0
            const float v10 = c[mt][cn][2] + b0, v11 = c[mt][cn][3] + b1;  // row r0+8
            if (MODE == 0) {
                *(float2*)&Cf[(size_t)r0 * N + c0]       = make_float2(v00, v01);
                *(float2*)&Cf[(size_t)(r0 + 8) * N + c0] = make_float2(v10, v11);
            } else if (MODE == 1) {
                const int h = c0 >> 6, dd = c0 & 63;
#pragma unroll
                for (int rr = 0; rr < 2; ++rr) {
                    const int r = r0 + rr * 8;
                    const int bb = r >> 11, s = r & (S_LEN - 1);
                    const size_t base = (((size_t)(bb * NHEADS + h)) * S_LEN + s) * DHEAD + dd;
                    const float x0 = rr ? v10 : v00, x1 = rr ? v11 : v01;
                    *(uint32_t*)&Ch[base] = pack2h(__float2half(x0), __float2half(x1));
                }
            } else {  // MODE 2: [bh][d][s]
                const int h = c0 >> 6, dd = c0 & 63;
#pragma unroll
                for (int rr = 0; rr < 2; ++rr) {
                    const int r = r0 + rr * 8;
                    const int bb = r >> 11, s = r & (S_LEN - 1);
                    const size_t base = (((size_t)(bb * NHEADS + h)) * DHEAD + dd) * S_LEN + s;
                    const float x0 = rr ? v10 : v00, x1 = rr ? v11 : v01;
                    Ch[base]         = __float2half(x0);
                    Ch[base + S_LEN] = __float2half(x1);
                }
            }
        }
    }
}

// ----------------------------------------------------------------------------
// Banded flash attention, single fp16 on mma.sync. 4 warps, 64q x 64k tiles.
// Warp = 16 query rows. P stays in registers (QK d-frag == PV a-frag layout).
// ----------------------------------------------------------------------------
constexpr int ATT_LD = 144;                  // bytes per smem row (64 fp16 + 8 pad)
constexpr int SM_Q   = 0;
constexpr int SM_K   = SM_Q + 64 * ATT_LD;
constexpr int SM_V   = SM_K + 64 * ATT_LD;
constexpr int ATT_SMEM = SM_V + 64 * ATT_LD; // 27648 B

__global__ __launch_bounds__(128)
void attn_kernel()
{
    extern __shared__ char sm[];
    const uint32_t sb = smem_u32(sm);
    const int tid  = threadIdx.x;
    const int lane = tid & 31;
    const int w    = tid >> 5;          // 0..3 : query rows w*16..w*16+15
    const int bh   = blockIdx.y;
    const int qb   = blockIdx.x;
    const int qi0  = qb << 6;

    const __half* Qp = g_q + (size_t)bh * S_LEN * DHEAD;
    const __half* Kp = g_k + (size_t)bh * DHEAD * S_LEN;
    const __half* Vp = g_v + (size_t)bh * S_LEN * DHEAD;

    // ---- load Q tile (rows qi0..qi0+63): 64 rows x 8 x 16B segments --------
#pragma unroll
    for (int it = 0; it < 4; ++it) {
        const int idx = tid + it * 128;          // 0..511
        const int row = idx >> 3, seg = idx & 7;
        *(uint4*)(sm + SM_Q + row * ATT_LD + seg * 16) =
            *(const uint4*)(Qp + (size_t)(qi0 + row) * DHEAD + seg * 8);
    }
    __syncthreads();

    // ---- Q fragments (constant across chunks) ------------------------------
    const int lr = lane & 15, lc = lane >> 4;
    uint32_t aq[4][4];
    {
        const uint32_t qoff = sb + SM_Q + (w * 16 + lr) * ATT_LD + lc * 16;
#pragma unroll
        for (int kt = 0; kt < 4; ++kt) ldsm_x4(aq[kt], qoff + kt * 32);
    }

    const int row0 = qi0 + w * 16 + (lane >> 2);
    const int row1 = row0 + 8;
    const int colq = (lane & 3) * 2;

    float m0 = -1e30f, m1 = -1e30f, l0 = 0.f, l1 = 0.f;
    float o[8][4];
#pragma unroll
    for (int nt = 0; nt < 8; ++nt)
#pragma unroll
        for (int e = 0; e < 4; ++e) o[nt][e] = 0.f;

    // ---- chunk schedule ----------------------------------------------------
    int lo = qi0 - WIN;        if (lo < 0) lo = 0;
    int hi = qi0 + 63 + WIN;   if (hi > S_LEN - 1) hi = S_LEN - 1;
    int c_lo = lo >> 6;
    int c_hi = hi >> 6;
    if (qb == 0) c_hi = (S_LEN >> 6) - 1;   // row 0 is global: all chunks
    const int start = (c_lo < 1) ? 1 : c_lo;
    const int nch   = (c_hi - start + 1) + 1;

    const uint32_t kvoff = sb + lr * ATT_LD + lc * 16;

    for (int ci = 0; ci < nch; ++ci) {
        const int ck = (ci == 0) ? 0 : (start + ci - 1);
        const int kb = ck << 6;

        __syncthreads();   // previous chunk's ldsm reads complete
        // K chunk [d][key] (gmem already transposed) + V chunk [key][d]
#pragma unroll
        for (int it = 0; it < 4; ++it) {
            const int idx = tid + it * 128;      // 0..511
            const int row = idx >> 3, seg = idx & 7;
            *(uint4*)(sm + SM_K + row * ATT_LD + seg * 16) =
                *(const uint4*)(Kp + (size_t)row * S_LEN + kb + seg * 8);
            *(uint4*)(sm + SM_V + row * ATT_LD + seg * 16) =
                *(const uint4*)(Vp + (size_t)(kb + row) * DHEAD + seg * 8);
        }
        __syncthreads();

        // ---- scores: S = Q K^T -------------------------------------------
        float s[8][4];
#pragma unroll
        for (int nt = 0; nt < 8; ++nt)
#pragma unroll
            for (int e = 0; e < 4; ++e) s[nt][e] = 0.f;

#pragma unroll
        for (int nt4 = 0; nt4 < 4; ++nt4) {
#pragma unroll
            for (int kt = 0; kt < 4; ++kt) {
                uint32_t bk[4];
                ldsm_x4_t(bk, kvoff + SM_K + kt * (16 * ATT_LD) + nt4 * 32);
#pragma unroll
                for (int hh = 0; hh < 2; ++hh)
                    mma16816h(s[nt4 * 2 + hh], aq[kt], bk[2 * hh], bk[2 * hh + 1]);
            }
        }

        // ---- mask + scale + online softmax --------------------------------
        float mx0 = -1e30f, mx1 = -1e30f;
#pragma unroll
        for (int nt = 0; nt < 8; ++nt) {
            const int cb = kb + nt * 8 + colq;
#pragma unroll
            for (int oo = 0; oo < 2; ++oo) {
                const int cc = cb + oo;
                int d0 = row0 - cc; d0 = (d0 < 0) ? -d0 : d0;
                int d1 = row1 - cc; d1 = (d1 < 0) ? -d1 : d1;
                const bool ok0 = (d0 <= WIN) | (row0 == 0) | (cc == 0);
                const bool ok1 = (d1 <= WIN) | (row1 == 0) | (cc == 0);
                s[nt][oo]     = ok0 ? s[nt][oo]     * 0.125f : -1e30f;
                s[nt][2 + oo] = ok1 ? s[nt][2 + oo] * 0.125f : -1e30f;
                mx0 = fmaxf(mx0, s[nt][oo]);
                mx1 = fmaxf(mx1, s[nt][2 + oo]);
            }
        }
        mx0 = fmaxf(mx0, __shfl_xor_sync(0xffffffffu, mx0, 1));
        mx0 = fmaxf(mx0, __shfl_xor_sync(0xffffffffu, mx0, 2));
        mx1 = fmaxf(mx1, __shfl_xor_sync(0xffffffffu, mx1, 1));
        mx1 = fmaxf(mx1, __shfl_xor_sync(0xffffffffu, mx1, 2));

        const float mn0 = fmaxf(m0, mx0), mn1 = fmaxf(m1, mx1);
        const float cf0 = __expf(m0 - mn0), cf1 = __expf(m1 - mn1);
        m0 = mn0; m1 = mn1;

        float rs0 = 0.f, rs1 = 0.f;
#pragma unroll
        for (int nt = 0; nt < 8; ++nt) {
            s[nt][0] = __expf(s[nt][0] - mn0);
            s[nt][1] = __expf(s[nt][1] - mn0);
            s[nt][2] = __expf(s[nt][2] - mn1);
            s[nt][3] = __expf(s[nt][3] - mn1);
            rs0 += s[nt][0] + s[nt][1];
            rs1 += s[nt][2] + s[nt][3];
        }
        rs0 += __shfl_xor_sync(0xffffffffu, rs0, 1);
        rs0 += __shfl_xor_sync(0xffffffffu, rs0, 2);
        rs1 += __shfl_xor_sync(0xffffffffu, rs1, 1);
        rs1 += __shfl_xor_sync(0xffffffffu, rs1, 2);
        l0 = l0 * cf0 + rs0;
        l1 = l1 * cf1 + rs1;
#pragma unroll
        for (int nt = 0; nt < 8; ++nt) {
            o[nt][0] *= cf0; o[nt][1] *= cf0;
            o[nt][2] *= cf1; o[nt][3] *= cf1;
        }

        // ---- PV: O += P V  (P frags built in registers, fp16 single) ------
#pragma unroll
        for (int kt = 0; kt < 4; ++kt) {
            uint32_t ap[4];
            ap[0] = pack2h(__float2half(s[2 * kt][0]),     __float2half(s[2 * kt][1]));
            ap[1] = pack2h(__float2half(s[2 * kt][2]),     __float2half(s[2 * kt][3]));
            ap[2] = pack2h(__float2half(s[2 * kt + 1][0]), __float2half(s[2 * kt + 1][1]));
            ap[3] = pack2h(__float2half(s[2 * kt + 1][2]), __float2half(s[2 * kt + 1][3]));
#pragma unroll
            for (int nd4 = 0; nd4 < 4; ++nd4) {
                uint32_t bv[4];
                ldsm_x4_t(bv, kvoff + SM_V + kt * (16 * ATT_LD) + nd4 * 32);
#pragma unroll
                for (int hh = 0; hh < 2; ++hh)
                    mma16816h(o[nd4 * 2 + hh], ap, bv[2 * hh], bv[2 * hh + 1]);
            }
        }
    }

    // ---- normalize + write fp16, token-major [B,S,H*d] ---------------------
    const int b = bh >> 4, h = bh & 15;
    const float i0 = 1.f / l0, i1 = 1.f / l1;
#pragma unroll
    for (int nt = 0; nt < 8; ++nt) {
        const int dd = h * DHEAD + nt * 8 + colq;
        {
            const size_t base = ((size_t)(b * S_LEN + row0)) * D_MODEL + dd;
            *(uint32_t*)&g_att[base] =
                pack2h(__float2half(o[nt][0] * i0), __float2half(o[nt][1] * i0));
        }
        {
            const size_t base = ((size_t)(b * S_LEN + row1)) * D_MODEL + dd;
            *(uint32_t*)&g_att[base] =
                pack2h(__float2half(o[nt][2] * i1), __float2half(o[nt][3] * i1));
        }
    }
}

// ----------------------------------------------------------------------------
extern "C" void kernel_launch(void* const* d_in, const int* in_sizes, int n_in,
                              void* d_out, int out_size)
{
    (void)in_sizes; (void)n_in; (void)out_size;
    const float* x  = (const float*)d_in[0];
    const float* Wq = (const float*)d_in[1];
    const float* bq = (const float*)d_in[2];
    const float* Wk = (const float*)d_in[3];
    const float* bk = (const float*)d_in[4];
    const float* Wv = (const float*)d_in[5];
    const float* bv = (const float*)d_in[6];
    const float* Wo = (const float*)d_in[7];
    const float* bo = (const float*)d_in[8];
    float* out = (float*)d_out;

    __half *xh, *wh, *wl, *q, *k, *v, *att;
    cudaGetSymbolAddress((void**)&xh,  g_xh);
    cudaGetSymbolAddress((void**)&wh,  g_wh);
    cudaGetSymbolAddress((void**)&wl,  g_wl);
    cudaGetSymbolAddress((void**)&q,   g_q);
    cudaGetSymbolAddress((void**)&k,   g_k);
    cudaGetSymbolAddress((void**)&v,   g_v);
    cudaGetSymbolAddress((void**)&att, g_att);

    cudaFuncSetAttribute(attn_kernel, cudaFuncAttributeMaxDynamicSharedMemorySize, ATT_SMEM);

    constexpr int NW = D_MODEL * D_MODEL;

    splitx_kernel<<<M_TOK * D_MODEL / 1024, 256>>>(x, xh, M_TOK * D_MODEL);
    splitw_kernel<<<dim3(NW / 1024, 4), 256>>>(Wq, Wk, Wv, Wo, wh, wl);

    const dim3 gg(D_MODEL / 128, M_TOK / 128);   // (8, 32)
    gemm_fp16x2<1><<<gg, 256>>>(xh, wh + 0 * NW, wl + 0 * NW, bq, nullptr, q);
    gemm_fp16x2<2><<<gg, 256>>>(xh, wh + 1 * NW, wl + 1 * NW, bk, nullptr, k);
    gemm_fp16x2<1><<<gg, 256>>>(xh, wh + 2 * NW, wl + 2 * NW, bv, nullptr, v);

    attn_kernel<<<dim3(S_LEN / 64, BATCH * NHEADS), 128, ATT_SMEM>>>();

    gemm_fp16x2<0><<<gg, 256>>>(att, wh + 3 * NW, wl + 3 * NW, bo, out, nullptr);
}

// round 14
// speedup vs baseline: 2.1206x; 2.1206x over previous
#include <cuda_runtime.h>
#include <cuda_fp16.h>
#include <cstdint>

// ============================================================================
// Longformer attention, all single-fp16 tensor-core path (fp32 accumulate).
//   QKV projections fused in one launch (grid.z selects weight + epilogue).
//   Flash attention with P in registers (R13-validated core).
// ============================================================================

constexpr int D_MODEL = 1024;
constexpr int S_LEN   = 2048;
constexpr int BATCH   = 2;
constexpr int NHEADS  = 16;
constexpr int DHEAD   = 64;
constexpr int M_TOK   = BATCH * S_LEN;   // 4096
constexpr int WIN     = 256;
constexpr int NW      = D_MODEL * D_MODEL;

// scratch (device globals: no allocation allowed)
__device__ __half g_xh[M_TOK * D_MODEL];                 // x as fp16
__device__ __half g_wh[4 * NW];                          // W [K,N] fp16 (4 weights)
__device__ __half g_q[BATCH * NHEADS * S_LEN * DHEAD];   // [bh][s][d]
__device__ __half g_k[BATCH * NHEADS * DHEAD * S_LEN];   // [bh][d][s] (transposed)
__device__ __half g_v[BATCH * NHEADS * S_LEN * DHEAD];   // [bh][s][d]
__device__ __half g_att[M_TOK * D_MODEL];                // attention out fp16

// ----------------------------------------------------------------------------
// helpers
// ----------------------------------------------------------------------------
__device__ __forceinline__ uint32_t smem_u32(const void* p) {
    return (uint32_t)__cvta_generic_to_shared(p);
}
__device__ __forceinline__ void ldsm_x4(uint32_t (&r)[4], uint32_t addr) {
    asm volatile("ldmatrix.sync.aligned.m8n8.x4.shared.b16 {%0,%1,%2,%3}, [%4];"
                 : "=r"(r[0]), "=r"(r[1]), "=r"(r[2]), "=r"(r[3]) : "r"(addr));
}
__device__ __forceinline__ void ldsm_x4_t(uint32_t (&r)[4], uint32_t addr) {
    asm volatile("ldmatrix.sync.aligned.m8n8.x4.trans.shared.b16 {%0,%1,%2,%3}, [%4];"
                 : "=r"(r[0]), "=r"(r[1]), "=r"(r[2]), "=r"(r[3]) : "r"(addr));
}
__device__ __forceinline__ void mma16816h(float (&d)[4], const uint32_t (&a)[4],
                                          uint32_t b0, uint32_t b1) {
    asm volatile("mma.sync.aligned.m16n8k16.row.col.f32.f16.f16.f32 "
                 "{%0,%1,%2,%3}, {%4,%5,%6,%7}, {%8,%9}, {%0,%1,%2,%3};"
                 : "+f"(d[0]), "+f"(d[1]), "+f"(d[2]), "+f"(d[3])
                 : "r"(a[0]), "r"(a[1]), "r"(a[2]), "r"(a[3]), "r"(b0), "r"(b1));
}
__device__ __forceinline__ uint32_t pack2h(__half a, __half b) {
    uint16_t x = *(uint16_t*)&a, y = *(uint16_t*)&b;
    return (uint32_t)x | ((uint32_t)y << 16);
}

// ----------------------------------------------------------------------------
// x: fp32 -> fp16
// ----------------------------------------------------------------------------
__global__ void splitx_kernel(const float* __restrict__ s, __half* __restrict__ h, int n)
{
    const int i = (blockIdx.x * blockDim.x + threadIdx.x) * 4;
    if (i >= n) return;
    float4 v = *(const float4*)(s + i);
    __align__(8) __half hh[4] = { __float2half(v.x), __float2half(v.y),
                                  __float2half(v.z), __float2half(v.w) };
    *(uint2*)&h[i] = *(uint2*)hh;
}

// ----------------------------------------------------------------------------
// W: fp32 -> fp16. All 4 weights in one launch (grid.y).
// ----------------------------------------------------------------------------
__global__ void splitw_kernel(const float* __restrict__ W0, const float* __restrict__ W1,
                              const float* __restrict__ W2, const float* __restrict__ W3,
                              __half* __restrict__ h)
{
    const int wsel = blockIdx.y;
    const float* W = (wsel == 0) ? W0 : (wsel == 1) ? W1 : (wsel == 2) ? W2 : W3;
    const int i = (blockIdx.x * blockDim.x + threadIdx.x) * 4;
    if (i >= NW) return;
    float4 v = *(const float4*)(W + i);
    __align__(8) __half hh[4] = { __float2half(v.x), __float2half(v.y),
                                  __float2half(v.z), __float2half(v.w) };
    *(uint2*)&h[(size_t)wsel * NW + i] = *(uint2*)hh;
}

// ----------------------------------------------------------------------------
// single-fp16 GEMM: C[4096,1024] = A * W + bias,  W = [K,N], fp32 accum.
// 128x128 tile, KSTEP 16, 256 thr = 8 warps (4m x 2n), warp 32x64.
// QKV=true : grid.z = 0/1/2 selects Wq/Wk/Wv; epilogue fp16 split-head
//            (z==1 -> K transposed [bh][d][s], else [bh][s][d])
// QKV=false: fp32 row-major [M,N] (final projection -> d_out)
// ----------------------------------------------------------------------------
template<bool QKV>
__global__ __launch_bounds__(256, 2)
void gemm_fp16(const __half* __restrict__ A, const __half* __restrict__ Wbase,
               const float* __restrict__ bq, const float* __restrict__ bk,
               const float* __restrict__ bv,
               float* __restrict__ Cf,
               __half* __restrict__ Cq, __half* __restrict__ Ck, __half* __restrict__ Cv)
{
    constexpr int K   = D_MODEL;
    constexpr int N   = D_MODEL;
    constexpr int LDA = 24;    // 16 + 8 pad
    constexpr int LDB = 136;   // 128 + 8 pad

    __shared__ __half As[2][128 * LDA];
    __shared__ __half Bs[2][16 * LDB];

    const int tid  = threadIdx.x;
    const int lane = tid & 31;
    const int w    = tid >> 5;
    const int wm   = w >> 1;
    const int wn   = w & 1;
    const int bm   = blockIdx.y * 128;
    const int bn   = blockIdx.x * 128;
    const int z    = QKV ? (int)blockIdx.z : 0;

    const __half* B = Wbase + (size_t)z * NW;
    const float* bias = QKV ? ((z == 0) ? bq : (z == 1) ? bk : bv) : bq;

    const int arow = tid >> 1, acol = (tid & 1) * 8;
    const int brow = tid >> 4, bcol = (tid & 15) * 8;
    const __half* Ap = A + (size_t)(bm + arow) * K + acol;
    const __half* Bp = B + (size_t)brow * N + bn + bcol;
    const int a_soff = arow * LDA + acol;
    const int b_soff = brow * LDB + bcol;

    const int lr = lane & 15, lc = lane >> 4;
    uint32_t aAddr[2][2];      // [buf][mt]
    uint32_t bAddr[2][4];      // [buf][nt]
#pragma unroll
    for (int b2 = 0; b2 < 2; ++b2) {
        uint32_t ab = smem_u32(&As[b2][0]);
        uint32_t bb = smem_u32(&Bs[b2][0]);
#pragma unroll
        for (int mt = 0; mt < 2; ++mt)
            aAddr[b2][mt] = ab + ((wm * 32 + mt * 16 + lr) * LDA + lc * 8) * 2;
#pragma unroll
        for (int nt = 0; nt < 4; ++nt)
            bAddr[b2][nt] = bb + (lr * LDB + wn * 64 + nt * 16 + lc * 8) * 2;
    }

    float c[2][8][4];
#pragma unroll
    for (int mt = 0; mt < 2; ++mt)
#pragma unroll
        for (int cn = 0; cn < 8; ++cn)
#pragma unroll
            for (int e = 0; e < 4; ++e) c[mt][cn][e] = 0.f;

    *(uint4*)&As[0][a_soff] = *(const uint4*)Ap;
    *(uint4*)&Bs[0][b_soff] = *(const uint4*)Bp;
    __syncthreads();

    int buf = 0;
    for (int t = 0; t < K / 16; ++t) {
        uint4 ra, rb;
        const bool pf = (t + 1) < K / 16;
        if (pf) {
            ra = *(const uint4*)(Ap + (t + 1) * 16);
            rb = *(const uint4*)(Bp + (size_t)(t + 1) * 16 * N);
        }

        uint32_t a_f[2][4];
#pragma unroll
        for (int mt = 0; mt < 2; ++mt) ldsm_x4(a_f[mt], aAddr[buf][mt]);
#pragma unroll
        for (int nt = 0; nt < 4; ++nt) {
            uint32_t b_f[4];
            ldsm_x4_t(b_f, bAddr[buf][nt]);
#pragma unroll
            for (int hh = 0; hh < 2; ++hh) {
                const int cn = nt * 2 + hh;
#pragma unroll
                for (int mt = 0; mt < 2; ++mt)
                    mma16816h(c[mt][cn], a_f[mt], b_f[2 * hh], b_f[2 * hh + 1]);
            }
        }

        if (pf) {
            const int nb = buf ^ 1;
            *(uint4*)&As[nb][a_soff] = ra;
            *(uint4*)&Bs[nb][b_soff] = rb;
        }
        __syncthreads();
        buf ^= 1;
    }

    // epilogue
    const int r_base = bm + wm * 32 + (lane >> 2);
    const int c_base = bn + wn * 64 + (lane & 3) * 2;
#pragma unroll
    for (int mt = 0; mt < 2; ++mt) {
#pragma unroll
        for (int cn = 0; cn < 8; ++cn) {
            const int r0 = r_base + mt * 16;
            const int c0 = c_base + cn * 8;
            const float b0 = bias[c0], b1 = bias[c0 + 1];
            const float v00 = c[mt][cn][0] + b0, v01 = c[mt][cn][1] + b1;  // row r0
            const float v10 = c[mt][cn][2] + b0, v11 = c[mt][cn][3] + b1;  // row r0+8
            if (!QKV) {
                *(float2*)&Cf[(size_t)r0 * N + c0]       = make_float2(v00, v01);
                *(float2*)&Cf[(size_t)(r0 + 8) * N + c0] = make_float2(v10, v11);
            } else if (z != 1) {   // Q or V: [bh][s][d]
                __half* C = (z == 0) ? Cq : Cv;
                const int h = c0 >> 6, dd = c0 & 63;
#pragma unroll
                for (int rr = 0; rr < 2; ++rr) {
                    const int r = r0 + rr * 8;
                    const int bb = r >> 11, s = r & (S_LEN - 1);
                    const size_t base = (((size_t)(bb * NHEADS + h)) * S_LEN + s) * DHEAD + dd;
                    const float x0 = rr ? v10 : v00, x1 = rr ? v11 : v01;
                    *(uint32_t*)&C[base] = pack2h(__float2half(x0), __float2half(x1));
                }
            } else {               // K: [bh][d][s]
                const int h = c0 >> 6, dd = c0 & 63;
#pragma unroll
                for (int rr = 0; rr < 2; ++rr) {
                    const int r = r0 + rr * 8;
                    const int bb = r >> 11, s = r & (S_LEN - 1);
                    const size_t base = (((size_t)(bb * NHEADS + h)) * DHEAD + dd) * S_LEN + s;
                    const float x0 = rr ? v10 : v00, x1 = rr ? v11 : v01;
                    Ck[base]         = __float2half(x0);
                    Ck[base + S_LEN] = __float2half(x1);
                }
            }
        }
    }
}

// ----------------------------------------------------------------------------
// Banded flash attention, single fp16 on mma.sync (R13-validated core).
// 4 warps, 64q x 64k tiles; warp = 16 query rows; P stays in registers.
// ----------------------------------------------------------------------------
constexpr int ATT_LD = 144;                  // bytes per smem row (64 fp16 + 8 pad)
constexpr int SM_Q   = 0;
constexpr int SM_K   = SM_Q + 64 * ATT_LD;
constexpr int SM_V   = SM_K + 64 * ATT_LD;
constexpr int ATT_SMEM = SM_V + 64 * ATT_LD; // 27648 B

__global__ __launch_bounds__(128)
void attn_kernel()
{
    extern __shared__ char sm[];
    const uint32_t sb = smem_u32(sm);
    const int tid  = threadIdx.x;
    const int lane = tid & 31;
    const int w    = tid >> 5;          // 0..3 : query rows w*16..w*16+15
    const int bh   = blockIdx.y;
    const int qb   = blockIdx.x;
    const int qi0  = qb << 6;

    const __half* Qp = g_q + (size_t)bh * S_LEN * DHEAD;
    const __half* Kp = g_k + (size_t)bh * DHEAD * S_LEN;
    const __half* Vp = g_v + (size_t)bh * S_LEN * DHEAD;

    // ---- load Q tile (rows qi0..qi0+63): 64 rows x 8 x 16B segments --------
#pragma unroll
    for (int it = 0; it < 4; ++it) {
        const int idx = tid + it * 128;          // 0..511
        const int row = idx >> 3, seg = idx & 7;
        *(uint4*)(sm + SM_Q + row * ATT_LD + seg * 16) =
            *(const uint4*)(Qp + (size_t)(qi0 + row) * DHEAD + seg * 8);
    }
    __syncthreads();

    // ---- Q fragments (constant across chunks) ------------------------------
    const int lr = lane & 15, lc = lane >> 4;
    uint32_t aq[4][4];
    {
        const uint32_t qoff = sb + SM_Q + (w * 16 + lr) * ATT_LD + lc * 16;
#pragma unroll
        for (int kt = 0; kt < 4; ++kt) ldsm_x4(aq[kt], qoff + kt * 32);
    }

    const int row0 = qi0 + w * 16 + (lane >> 2);
    const int row1 = row0 + 8;
    const int colq = (lane & 3) * 2;

    float m0 = -1e30f, m1 = -1e30f, l0 = 0.f, l1 = 0.f;
    float o[8][4];
#pragma unroll
    for (int nt = 0; nt < 8; ++nt)
#pragma unroll
        for (int e = 0; e < 4; ++e) o[nt][e] = 0.f;

    // ---- chunk schedule ----------------------------------------------------
    int lo = qi0 - WIN;        if (lo < 0) lo = 0;
    int hi = qi0 + 63 + WIN;   if (hi > S_LEN - 1) hi = S_LEN - 1;
    int c_lo = lo >> 6;
    int c_hi = hi >> 6;
    if (qb == 0) c_hi = (S_LEN >> 6) - 1;   // row 0 is global: all chunks
    const int start = (c_lo < 1) ? 1 : c_lo;
    const int nch   = (c_hi - start + 1) + 1;

    const uint32_t kvoff = sb + lr * ATT_LD + lc * 16;

    for (int ci = 0; ci < nch; ++ci) {
        const int ck = (ci == 0) ? 0 : (start + ci - 1);
        const int kb = ck << 6;

        __syncthreads();   // previous chunk's ldsm reads complete
        // K chunk [d][key] (gmem already transposed) + V chunk [key][d]
#pragma unroll
        for (int it = 0; it < 4; ++it) {
            const int idx = tid + it * 128;      // 0..511
            const int row = idx >> 3, seg = idx & 7;
            *(uint4*)(sm + SM_K + row * ATT_LD + seg * 16) =
                *(const uint4*)(Kp + (size_t)row * S_LEN + kb + seg * 8);
            *(uint4*)(sm + SM_V + row * ATT_LD + seg * 16) =
                *(const uint4*)(Vp + (size_t)(kb + row) * DHEAD + seg * 8);
        }
        __syncthreads();

        // ---- scores: S = Q K^T -------------------------------------------
        float s[8][4];
#pragma unroll
        for (int nt = 0; nt < 8; ++nt)
#pragma unroll
            for (int e = 0; e < 4; ++e) s[nt][e] = 0.f;

#pragma unroll
        for (int nt4 = 0; nt4 < 4; ++nt4) {
#pragma unroll
            for (int kt = 0; kt < 4; ++kt) {
                uint32_t bk[4];
                ldsm_x4_t(bk, kvoff + SM_K + kt * (16 * ATT_LD) + nt4 * 32);
#pragma unroll
                for (int hh = 0; hh < 2; ++hh)
                    mma16816h(s[nt4 * 2 + hh], aq[kt], bk[2 * hh], bk[2 * hh + 1]);
            }
        }

        // ---- mask + scale + online softmax --------------------------------
        float mx0 = -1e30f, mx1 = -1e30f;
#pragma unroll
        for (int nt = 0; nt < 8; ++nt) {
            const int cb = kb + nt * 8 + colq;
#pragma unroll
            for (int oo = 0; oo < 2; ++oo) {
                const int cc = cb + oo;
                int d0 = row0 - cc; d0 = (d0 < 0) ? -d0 : d0;
                int d1 = row1 - cc; d1 = (d1 < 0) ? -d1 : d1;
                const bool ok0 = (d0 <= WIN) | (row0 == 0) | (cc == 0);
                const bool ok1 = (d1 <= WIN) | (row1 == 0) | (cc == 0);
                s[nt][oo]     = ok0 ? s[nt][oo]     * 0.125f : -1e30f;
                s[nt][2 + oo] = ok1 ? s[nt][2 + oo] * 0.125f : -1e30f;
                mx0 = fmaxf(mx0, s[nt][oo]);
                mx1 = fmaxf(mx1, s[nt][2 + oo]);
            }
        }
        mx0 = fmaxf(mx0, __shfl_xor_sync(0xffffffffu, mx0, 1));
        mx0 = fmaxf(mx0, __shfl_xor_sync(0xffffffffu, mx0, 2));
        mx1 = fmaxf(mx1, __shfl_xor_sync(0xffffffffu, mx1, 1));
        mx1 = fmaxf(mx1, __shfl_xor_sync(0xffffffffu, mx1, 2));

        const float mn0 = fmaxf(m0, mx0), mn1 = fmaxf(m1, mx1);
        const float cf0 = __expf(m0 - mn0), cf1 = __expf(m1 - mn1);
        m0 = mn0; m1 = mn1;

        float rs0 = 0.f, rs1 = 0.f;
#pragma unroll
        for (int nt = 0; nt < 8; ++nt) {
            s[nt][0] = __expf(s[nt][0] - mn0);
            s[nt][1] = __expf(s[nt][1] - mn0);
            s[nt][2] = __expf(s[nt][2] - mn1);
            s[nt][3] = __expf(s[nt][3] - mn1);
            rs0 += s[nt][0] + s[nt][1];
            rs1 += s[nt][2] + s[nt][3];
        }
        rs0 += __shfl_xor_sync(0xffffffffu, rs0, 1);
        rs0 += __shfl_xor_sync(0xffffffffu, rs0, 2);
        rs1 += __shfl_xor_sync(0xffffffffu, rs1, 1);
        rs1 += __shfl_xor_sync(0xffffffffu, rs1, 2);
        l0 = l0 * cf0 + rs0;
        l1 = l1 * cf1 + rs1;
#pragma unroll
        for (int nt = 0; nt < 8; ++nt) {
            o[nt][0] *= cf0; o[nt][1] *= cf0;
            o[nt][2] *= cf1; o[nt][3] *= cf1;
        }

        // ---- PV: O += P V  (P frags built in registers, fp16 single) ------
#pragma unroll
        for (int kt = 0; kt < 4; ++kt) {
            uint32_t ap[4];
            ap[0] = pack2h(__float2half(s[2 * kt][0]),     __float2half(s[2 * kt][1]));
            ap[1] = pack2h(__float2half(s[2 * kt][2]),     __float2half(s[2 * kt][3]));
            ap[2] = pack2h(__float2half(s[2 * kt + 1][0]), __float2half(s[2 * kt + 1][1]));
            ap[3] = pack2h(__float2half(s[2 * kt + 1][2]), __float2half(s[2 * kt + 1][3]));
#pragma unroll
            for (int nd4 = 0; nd4 < 4; ++nd4) {
                uint32_t bv[4];
                ldsm_x4_t(bv, kvoff + SM_V + kt * (16 * ATT_LD) + nd4 * 32);
#pragma unroll
                for (int hh = 0; hh < 2; ++hh)
                    mma16816h(o[nd4 * 2 + hh], ap, bv[2 * hh], bv[2 * hh + 1]);
            }
        }
    }

    // ---- normalize + write fp16, token-major [B,S,H*d] ---------------------
    const int b = bh >> 4, h = bh & 15;
    const float i0 = 1.f / l0, i1 = 1.f / l1;
#pragma unroll
    for (int nt = 0; nt < 8; ++nt) {
        const int dd = h * DHEAD + nt * 8 + colq;
        {
            const size_t base = ((size_t)(b * S_LEN + row0)) * D_MODEL + dd;
            *(uint32_t*)&g_att[base] =
                pack2h(__float2half(o[nt][0] * i0), __float2half(o[nt][1] * i0));
        }
        {
            const size_t base = ((size_t)(b * S_LEN + row1)) * D_MODEL + dd;
            *(uint32_t*)&g_att[base] =
                pack2h(__float2half(o[nt][2] * i1), __float2half(o[nt][3] * i1));
        }
    }
}

// ----------------------------------------------------------------------------
extern "C" void kernel_launch(void* const* d_in, const int* in_sizes, int n_in,
                              void* d_out, int out_size)
{
    (void)in_sizes; (void)n_in; (void)out_size;
    const float* x  = (const float*)d_in[0];
    const float* Wq = (const float*)d_in[1];
    const float* bq = (const float*)d_in[2];
    const float* Wk = (const float*)d_in[3];
    const float* bk = (const float*)d_in[4];
    const float* Wv = (const float*)d_in[5];
    const float* bv = (const float*)d_in[6];
    const float* Wo = (const float*)d_in[7];
    const float* bo = (const float*)d_in[8];
    float* out = (float*)d_out;

    __half *xh, *wh, *q, *k, *v, *att;
    cudaGetSymbolAddress((void**)&xh,  g_xh);
    cudaGetSymbolAddress((void**)&wh,  g_wh);
    cudaGetSymbolAddress((void**)&q,   g_q);
    cudaGetSymbolAddress((void**)&k,   g_k);
    cudaGetSymbolAddress((void**)&v,   g_v);
    cudaGetSymbolAddress((void**)&att, g_att);

    cudaFuncSetAttribute(attn_kernel, cudaFuncAttributeMaxDynamicSharedMemorySize, ATT_SMEM);

    splitx_kernel<<<M_TOK * D_MODEL / 1024, 256>>>(x, xh, M_TOK * D_MODEL);
    splitw_kernel<<<dim3(NW / 1024, 4), 256>>>(Wq, Wk, Wv, Wo, wh);

    // fused QKV projections: grid.z = 0/1/2 -> Q/K/V
    gemm_fp16<true><<<dim3(D_MODEL / 128, M_TOK / 128, 3), 256>>>(
        xh, wh, bq, bk, bv, nullptr, q, k, v);

    attn_kernel<<<dim3(S_LEN / 64, BATCH * NHEADS), 128, ATT_SMEM>>>();

    // final projection (Wo is 4th weight in g_wh)
    gemm_fp16<false><<<dim3(D_MODEL / 128, M_TOK / 128), 256>>>(
        att, wh + 3 * (size_t)NW, bo, nullptr, nullptr, out, nullptr, nullptr, nullptr);
}

// round 15
// speedup vs baseline: 2.1821x; 1.0290x over previous
#include <cuda_runtime.h>
#include <cuda_fp16.h>
#include <cstdint>

// ============================================================================
// Longformer attention, all single-fp16 tensor-core path (fp32 accumulate).
//   QKV projections fused in one launch (grid.z selects weight + epilogue).
//   Flash attention: balanced window tiles + dedicated global-row kernel.
// ============================================================================

constexpr int D_MODEL = 1024;
constexpr int S_LEN   = 2048;
constexpr int BATCH   = 2;
constexpr int NHEADS  = 16;
constexpr int DHEAD   = 64;
constexpr int M_TOK   = BATCH * S_LEN;   // 4096
constexpr int WIN     = 256;
constexpr int NW      = D_MODEL * D_MODEL;

// scratch (device globals: no allocation allowed)
__device__ __half g_xh[M_TOK * D_MODEL];                 // x as fp16
__device__ __half g_wh[4 * NW];                          // W [K,N] fp16 (4 weights)
__device__ __half g_q[BATCH * NHEADS * S_LEN * DHEAD];   // [bh][s][d]
__device__ __half g_k[BATCH * NHEADS * DHEAD * S_LEN];   // [bh][d][s] (transposed)
__device__ __half g_v[BATCH * NHEADS * S_LEN * DHEAD];   // [bh][s][d]
__device__ __half g_att[M_TOK * D_MODEL];                // attention out fp16

// ----------------------------------------------------------------------------
// helpers
// ----------------------------------------------------------------------------
__device__ __forceinline__ uint32_t smem_u32(const void* p) {
    return (uint32_t)__cvta_generic_to_shared(p);
}
__device__ __forceinline__ void ldsm_x4(uint32_t (&r)[4], uint32_t addr) {
    asm volatile("ldmatrix.sync.aligned.m8n8.x4.shared.b16 {%0,%1,%2,%3}, [%4];"
                 : "=r"(r[0]), "=r"(r[1]), "=r"(r[2]), "=r"(r[3]) : "r"(addr));
}
__device__ __forceinline__ void ldsm_x4_t(uint32_t (&r)[4], uint32_t addr) {
    asm volatile("ldmatrix.sync.aligned.m8n8.x4.trans.shared.b16 {%0,%1,%2,%3}, [%4];"
                 : "=r"(r[0]), "=r"(r[1]), "=r"(r[2]), "=r"(r[3]) : "r"(addr));
}
__device__ __forceinline__ void mma16816h(float (&d)[4], const uint32_t (&a)[4],
                                          uint32_t b0, uint32_t b1) {
    asm volatile("mma.sync.aligned.m16n8k16.row.col.f32.f16.f16.f32 "
                 "{%0,%1,%2,%3}, {%4,%5,%6,%7}, {%8,%9}, {%0,%1,%2,%3};"
                 : "+f"(d[0]), "+f"(d[1]), "+f"(d[2]), "+f"(d[3])
                 : "r"(a[0]), "r"(a[1]), "r"(a[2]), "r"(a[3]), "r"(b0), "r"(b1));
}
__device__ __forceinline__ uint32_t pack2h(__half a, __half b) {
    uint16_t x = *(uint16_t*)&a, y = *(uint16_t*)&b;
    return (uint32_t)x | ((uint32_t)y << 16);
}

// ----------------------------------------------------------------------------
// x: fp32 -> fp16
// ----------------------------------------------------------------------------
__global__ void splitx_kernel(const float* __restrict__ s, __half* __restrict__ h, int n)
{
    const int i = (blockIdx.x * blockDim.x + threadIdx.x) * 4;
    if (i >= n) return;
    float4 v = *(const float4*)(s + i);
    __align__(8) __half hh[4] = { __float2half(v.x), __float2half(v.y),
                                  __float2half(v.z), __float2half(v.w) };
    *(uint2*)&h[i] = *(uint2*)hh;
}

// ----------------------------------------------------------------------------
// W: fp32 -> fp16. All 4 weights in one launch (grid.y).
// ----------------------------------------------------------------------------
__global__ void splitw_kernel(const float* __restrict__ W0, const float* __restrict__ W1,
                              const float* __restrict__ W2, const float* __restrict__ W3,
                              __half* __restrict__ h)
{
    const int wsel = blockIdx.y;
    const float* W = (wsel == 0) ? W0 : (wsel == 1) ? W1 : (wsel == 2) ? W2 : W3;
    const int i = (blockIdx.x * blockDim.x + threadIdx.x) * 4;
    if (i >= NW) return;
    float4 v = *(const float4*)(W + i);
    __align__(8) __half hh[4] = { __float2half(v.x), __float2half(v.y),
                                  __float2half(v.z), __float2half(v.w) };
    *(uint2*)&h[(size_t)wsel * NW + i] = *(uint2*)hh;
}

// ----------------------------------------------------------------------------
// single-fp16 GEMM (R14-validated): C[4096,1024] = A * W + bias,  W = [K,N]
// QKV=true : grid.z = 0/1/2 -> Wq/Wk/Wv; fp16 split-head epilogues
// QKV=false: fp32 row-major (final projection -> d_out)
// ----------------------------------------------------------------------------
template<bool QKV>
__global__ __launch_bounds__(256, 2)
void gemm_fp16(const __half* __restrict__ A, const __half* __restrict__ Wbase,
               const float* __restrict__ bq, const float* __restrict__ bk,
               const float* __restrict__ bv,
               float* __restrict__ Cf,
               __half* __restrict__ Cq, __half* __restrict__ Ck, __half* __restrict__ Cv)
{
    constexpr int K   = D_MODEL;
    constexpr int N   = D_MODEL;
    constexpr int LDA = 24;    // 16 + 8 pad
    constexpr int LDB = 136;   // 128 + 8 pad

    __shared__ __half As[2][128 * LDA];
    __shared__ __half Bs[2][16 * LDB];

    const int tid  = threadIdx.x;
    const int lane = tid & 31;
    const int w    = tid >> 5;
    const int wm   = w >> 1;
    const int wn   = w & 1;
    const int bm   = blockIdx.y * 128;
    const int bn   = blockIdx.x * 128;
    const int z    = QKV ? (int)blockIdx.z : 0;

    const __half* B = Wbase + (size_t)z * NW;
    const float* bias = QKV ? ((z == 0) ? bq : (z == 1) ? bk : bv) : bq;

    const int arow = tid >> 1, acol = (tid & 1) * 8;
    const int brow = tid >> 4, bcol = (tid & 15) * 8;
    const __half* Ap = A + (size_t)(bm + arow) * K + acol;
    const __half* Bp = B + (size_t)brow * N + bn + bcol;
    const int a_soff = arow * LDA + acol;
    const int b_soff = brow * LDB + bcol;

    const int lr = lane & 15, lc = lane >> 4;
    uint32_t aAddr[2][2];      // [buf][mt]
    uint32_t bAddr[2][4];      // [buf][nt]
#pragma unroll
    for (int b2 = 0; b2 < 2; ++b2) {
        uint32_t ab = smem_u32(&As[b2][0]);
        uint32_t bb = smem_u32(&Bs[b2][0]);
#pragma unroll
        for (int mt = 0; mt < 2; ++mt)
            aAddr[b2][mt] = ab + ((wm * 32 + mt * 16 + lr) * LDA + lc * 8) * 2;
#pragma unroll
        for (int nt = 0; nt < 4; ++nt)
            bAddr[b2][nt] = bb + (lr * LDB + wn * 64 + nt * 16 + lc * 8) * 2;
    }

    float c[2][8][4];
#pragma unroll
    for (int mt = 0; mt < 2; ++mt)
#pragma unroll
        for (int cn = 0; cn < 8; ++cn)
#pragma unroll
            for (int e = 0; e < 4; ++e) c[mt][cn][e] = 0.f;

    *(uint4*)&As[0][a_soff] = *(const uint4*)Ap;
    *(uint4*)&Bs[0][b_soff] = *(const uint4*)Bp;
    __syncthreads();

    int buf = 0;
    for (int t = 0; t < K / 16; ++t) {
        uint4 ra, rb;
        const bool pf = (t + 1) < K / 16;
        if (pf) {
            ra = *(const uint4*)(Ap + (t + 1) * 16);
            rb = *(const uint4*)(Bp + (size_t)(t + 1) * 16 * N);
        }

        uint32_t a_f[2][4];
#pragma unroll
        for (int mt = 0; mt < 2; ++mt) ldsm_x4(a_f[mt], aAddr[buf][mt]);
#pragma unroll
        for (int nt = 0; nt < 4; ++nt) {
            uint32_t b_f[4];
            ldsm_x4_t(b_f, bAddr[buf][nt]);
#pragma unroll
            for (int hh = 0; hh < 2; ++hh) {
                const int cn = nt * 2 + hh;
#pragma unroll
                for (int mt = 0; mt < 2; ++mt)
                    mma16816h(c[mt][cn], a_f[mt], b_f[2 * hh], b_f[2 * hh + 1]);
            }
        }

        if (pf) {
            const int nb = buf ^ 1;
            *(uint4*)&As[nb][a_soff] = ra;
            *(uint4*)&Bs[nb][b_soff] = rb;
        }
        __syncthreads();
        buf ^= 1;
    }

    // epilogue
    const int r_base = bm + wm * 32 + (lane >> 2);
    const int c_base = bn + wn * 64 + (lane & 3) * 2;
#pragma unroll
    for (int mt = 0; mt < 2; ++mt) {
#pragma unroll
        for (int cn = 0; cn < 8; ++cn) {
            const int r0 = r_base + mt * 16;
            const int c0 = c_base + cn * 8;
            const float b0 = bias[c0], b1 = bias[c0 + 1];
            const float v00 = c[mt][cn][0] + b0, v01 = c[mt][cn][1] + b1;  // row r0
            const float v10 = c[mt][cn][2] + b0, v11 = c[mt][cn][3] + b1;  // row r0+8
            if (!QKV) {
                *(float2*)&Cf[(size_t)r0 * N + c0]       = make_float2(v00, v01);
                *(float2*)&Cf[(size_t)(r0 + 8) * N + c0] = make_float2(v10, v11);
            } else if (z != 1) {   // Q or V: [bh][s][d]
                __half* C = (z == 0) ? Cq : Cv;
                const int h = c0 >> 6, dd = c0 & 63;
#pragma unroll
                for (int rr = 0; rr < 2; ++rr) {
                    const int r = r0 + rr * 8;
                    const int bb = r >> 11, s = r & (S_LEN - 1);
                    const size_t base = (((size_t)(bb * NHEADS + h)) * S_LEN + s) * DHEAD + dd;
                    const float x0 = rr ? v10 : v00, x1 = rr ? v11 : v01;
                    *(uint32_t*)&C[base] = pack2h(__float2half(x0), __float2half(x1));
                }
            } else {               // K: [bh][d][s]
                const int h = c0 >> 6, dd = c0 & 63;
#pragma unroll
                for (int rr = 0; rr < 2; ++rr) {
                    const int r = r0 + rr * 8;
                    const int bb = r >> 11, s = r & (S_LEN - 1);
                    const size_t base = (((size_t)(bb * NHEADS + h)) * DHEAD + dd) * S_LEN + s;
                    const float x0 = rr ? v10 : v00, x1 = rr ? v11 : v01;
                    Ck[base]         = __float2half(x0);
                    Ck[base + S_LEN] = __float2half(x1);
                }
            }
        }
    }
}

// ----------------------------------------------------------------------------
// Banded flash attention, single fp16 on mma.sync. 4 warps, 64q x 64k tiles.
// Balanced: NO global-row handling here (row 0 overwritten by row0_kernel).
// Per-chunk uniform mask predicate; interior chunks skip mask ALU entirely.
// ----------------------------------------------------------------------------
constexpr int ATT_LD = 144;                  // bytes per smem row (64 fp16 + 8 pad)
constexpr int SM_Q   = 0;
constexpr int SM_K   = SM_Q + 64 * ATT_LD;
constexpr int SM_V   = SM_K + 64 * ATT_LD;
constexpr int ATT_SMEM = SM_V + 64 * ATT_LD; // 27648 B

__global__ __launch_bounds__(128)
void attn_kernel()
{
    extern __shared__ char sm[];
    const uint32_t sb = smem_u32(sm);
    const int tid  = threadIdx.x;
    const int lane = tid & 31;
    const int w    = tid >> 5;          // 0..3 : query rows w*16..w*16+15
    const int bh   = blockIdx.y;
    const int qb   = blockIdx.x;
    const int qi0  = qb << 6;

    const __half* Qp = g_q + (size_t)bh * S_LEN * DHEAD;
    const __half* Kp = g_k + (size_t)bh * DHEAD * S_LEN;
    const __half* Vp = g_v + (size_t)bh * S_LEN * DHEAD;

    // ---- load Q tile (rows qi0..qi0+63): 64 rows x 8 x 16B segments --------
#pragma unroll
    for (int it = 0; it < 4; ++it) {
        const int idx = tid + it * 128;          // 0..511
        const int row = idx >> 3, seg = idx & 7;
        *(uint4*)(sm + SM_Q + row * ATT_LD + seg * 16) =
            *(const uint4*)(Qp + (size_t)(qi0 + row) * DHEAD + seg * 8);
    }
    __syncthreads();

    // ---- Q fragments (constant across chunks) ------------------------------
    const int lr = lane & 15, lc = lane >> 4;
    uint32_t aq[4][4];
    {
        const uint32_t qoff = sb + SM_Q + (w * 16 + lr) * ATT_LD + lc * 16;
#pragma unroll
        for (int kt = 0; kt < 4; ++kt) ldsm_x4(aq[kt], qoff + kt * 32);
    }

    const int row0 = qi0 + w * 16 + (lane >> 2);
    const int row1 = row0 + 8;
    const int colq = (lane & 3) * 2;

    float m0 = -1e30f, m1 = -1e30f, l0 = 0.f, l1 = 0.f;
    float o[8][4];
#pragma unroll
    for (int nt = 0; nt < 8; ++nt)
#pragma unroll
        for (int e = 0; e < 4; ++e) o[nt][e] = 0.f;

    // ---- chunk schedule (window + prepended global-col chunk 0) ------------
    int lo = qi0 - WIN;        if (lo < 0) lo = 0;
    int hi = qi0 + 63 + WIN;   if (hi > S_LEN - 1) hi = S_LEN - 1;
    const int c_lo = lo >> 6;
    const int c_hi = hi >> 6;
    const int start = (c_lo < 1) ? 1 : c_lo;
    const int nch   = (c_hi - start + 1) + 1;   // +1 for chunk 0

    const uint32_t kvoff = sb + lr * ATT_LD + lc * 16;

    for (int ci = 0; ci < nch; ++ci) {
        const int ck = (ci == 0) ? 0 : (start + ci - 1);
        const int kb = ck << 6;
        const bool need_mask = ((qi0 + 63 - kb) > WIN) | ((kb + 63 - qi0) > WIN);

        __syncthreads();   // previous chunk's ldsm reads complete
        // K chunk [d][key] (gmem already transposed) + V chunk [key][d]
#pragma unroll
        for (int it = 0; it < 4; ++it) {
            const int idx = tid + it * 128;      // 0..511
            const int row = idx >> 3, seg = idx & 7;
            *(uint4*)(sm + SM_K + row * ATT_LD + seg * 16) =
                *(const uint4*)(Kp + (size_t)row * S_LEN + kb + seg * 8);
            *(uint4*)(sm + SM_V + row * ATT_LD + seg * 16) =
                *(const uint4*)(Vp + (size_t)(kb + row) * DHEAD + seg * 8);
        }
        __syncthreads();

        // ---- scores: S = Q K^T -------------------------------------------
        float s[8][4];
#pragma unroll
        for (int nt = 0; nt < 8; ++nt)
#pragma unroll
            for (int e = 0; e < 4; ++e) s[nt][e] = 0.f;

#pragma unroll
        for (int nt4 = 0; nt4 < 4; ++nt4) {
#pragma unroll
            for (int kt = 0; kt < 4; ++kt) {
                uint32_t bk[4];
                ldsm_x4_t(bk, kvoff + SM_K + kt * (16 * ATT_LD) + nt4 * 32);
#pragma unroll
                for (int hh = 0; hh < 2; ++hh)
                    mma16816h(s[nt4 * 2 + hh], aq[kt], bk[2 * hh], bk[2 * hh + 1]);
            }
        }

        // ---- mask (uniform per chunk) + scale + online softmax ------------
        float mx0 = -1e30f, mx1 = -1e30f;
        if (need_mask) {
#pragma unroll
            for (int nt = 0; nt < 8; ++nt) {
                const int cb = kb + nt * 8 + colq;
#pragma unroll
                for (int oo = 0; oo < 2; ++oo) {
                    const int cc = cb + oo;
                    int d0 = row0 - cc; d0 = (d0 < 0) ? -d0 : d0;
                    int d1 = row1 - cc; d1 = (d1 < 0) ? -d1 : d1;
                    const bool ok0 = (d0 <= WIN) | (cc == 0);
                    const bool ok1 = (d1 <= WIN) | (cc == 0);
                    s[nt][oo]     = ok0 ? s[nt][oo]     * 0.125f : -1e30f;
                    s[nt][2 + oo] = ok1 ? s[nt][2 + oo] * 0.125f : -1e30f;
                    mx0 = fmaxf(mx0, s[nt][oo]);
                    mx1 = fmaxf(mx1, s[nt][2 + oo]);
                }
            }
        } else {
#pragma unroll
            for (int nt = 0; nt < 8; ++nt) {
#pragma unroll
                for (int oo = 0; oo < 2; ++oo) {
                    s[nt][oo]     *= 0.125f;
                    s[nt][2 + oo] *= 0.125f;
                    mx0 = fmaxf(mx0, s[nt][oo]);
                    mx1 = fmaxf(mx1, s[nt][2 + oo]);
                }
            }
        }
        mx0 = fmaxf(mx0, __shfl_xor_sync(0xffffffffu, mx0, 1));
        mx0 = fmaxf(mx0, __shfl_xor_sync(0xffffffffu, mx0, 2));
        mx1 = fmaxf(mx1, __shfl_xor_sync(0xffffffffu, mx1, 1));
        mx1 = fmaxf(mx1, __shfl_xor_sync(0xffffffffu, mx1, 2));

        const float mn0 = fmaxf(m0, mx0), mn1 = fmaxf(m1, mx1);
        const float cf0 = __expf(m0 - mn0), cf1 = __expf(m1 - mn1);
        m0 = mn0; m1 = mn1;

        float rs0 = 0.f, rs1 = 0.f;
#pragma unroll
        for (int nt = 0; nt < 8; ++nt) {
            s[nt][0] = __expf(s[nt][0] - mn0);
            s[nt][1] = __expf(s[nt][1] - mn0);
            s[nt][2] = __expf(s[nt][2] - mn1);
            s[nt][3] = __expf(s[nt][3] - mn1);
            rs0 += s[nt][0] + s[nt][1];
            rs1 += s[nt][2] + s[nt][3];
        }
        rs0 += __shfl_xor_sync(0xffffffffu, rs0, 1);
        rs0 += __shfl_xor_sync(0xffffffffu, rs0, 2);
        rs1 += __shfl_xor_sync(0xffffffffu, rs1, 1);
        rs1 += __shfl_xor_sync(0xffffffffu, rs1, 2);
        l0 = l0 * cf0 + rs0;
        l1 = l1 * cf1 + rs1;
#pragma unroll
        for (int nt = 0; nt < 8; ++nt) {
            o[nt][0] *= cf0; o[nt][1] *= cf0;
            o[nt][2] *= cf1; o[nt][3] *= cf1;
        }

        // ---- PV: O += P V  (P frags built in registers, fp16 single) ------
#pragma unroll
        for (int kt = 0; kt < 4; ++kt) {
            uint32_t ap[4];
            ap[0] = pack2h(__float2half(s[2 * kt][0]),     __float2half(s[2 * kt][1]));
            ap[1] = pack2h(__float2half(s[2 * kt][2]),     __float2half(s[2 * kt][3]));
            ap[2] = pack2h(__float2half(s[2 * kt + 1][0]), __float2half(s[2 * kt + 1][1]));
            ap[3] = pack2h(__float2half(s[2 * kt + 1][2]), __float2half(s[2 * kt + 1][3]));
#pragma unroll
            for (int nd4 = 0; nd4 < 4; ++nd4) {
                uint32_t bv[4];
                ldsm_x4_t(bv, kvoff + SM_V + kt * (16 * ATT_LD) + nd4 * 32);
#pragma unroll
                for (int hh = 0; hh < 2; ++hh)
                    mma16816h(o[nd4 * 2 + hh], ap, bv[2 * hh], bv[2 * hh + 1]);
            }
        }
    }

    // ---- normalize + write fp16, token-major [B,S,H*d] ---------------------
    const int b = bh >> 4, h = bh & 15;
    const float i0 = 1.f / l0, i1 = 1.f / l1;
#pragma unroll
    for (int nt = 0; nt < 8; ++nt) {
        const int dd = h * DHEAD + nt * 8 + colq;
        {
            const size_t base = ((size_t)(b * S_LEN + row0)) * D_MODEL + dd;
            *(uint32_t*)&g_att[base] =
                pack2h(__float2half(o[nt][0] * i0), __float2half(o[nt][1] * i0));
        }
        {
            const size_t base = ((size_t)(b * S_LEN + row1)) * D_MODEL + dd;
            *(uint32_t*)&g_att[base] =
                pack2h(__float2half(o[nt][2] * i1), __float2half(o[nt][3] * i1));
        }
    }
}

// ----------------------------------------------------------------------------
// Global query row (token 0 of each sequence attends ALL keys). One block per
// (b,h); fp32 math; overwrites g_att row s=0. Runs after attn_kernel.
// ----------------------------------------------------------------------------
__global__ __launch_bounds__(256)
void row0_kernel()
{
    __shared__ float q0s[DHEAD];
    __shared__ float ps[S_LEN];       // probabilities (8 KB)
    __shared__ float red[256];
    __shared__ float osum[4][DHEAD];

    const int bh  = blockIdx.x;
    const int tid = threadIdx.x;
    const __half* Qp = g_q + (size_t)bh * S_LEN * DHEAD;   // row 0
    const __half* Kp = g_k + (size_t)bh * DHEAD * S_LEN;
    const __half* Vp = g_v + (size_t)bh * S_LEN * DHEAD;

    if (tid < DHEAD) q0s[tid] = __half2float(Qp[tid]) * 0.125f;
    __syncthreads();

    // scores for keys [tid*8, tid*8+8)
    float acc[8];
#pragma unroll
    for (int j = 0; j < 8; ++j) acc[j] = 0.f;
    const int c0 = tid * 8;
    for (int d = 0; d < DHEAD; ++d) {
        const float qd = q0s[d];
        const uint4 kv = *(const uint4*)(Kp + (size_t)d * S_LEN + c0);
        const __half* kh = (const __half*)&kv;
#pragma unroll
        for (int j = 0; j < 8; ++j) acc[j] = fmaf(qd, __half2float(kh[j]), acc[j]);
    }

    // block max
    float mx = acc[0];
#pragma unroll
    for (int j = 1; j < 8; ++j) mx = fmaxf(mx, acc[j]);
    red[tid] = mx; __syncthreads();
    for (int st = 128; st >= 1; st >>= 1) {
        if (tid < st) red[tid] = fmaxf(red[tid], red[tid + st]);
        __syncthreads();
    }
    mx = red[0]; __syncthreads();

    // exp + sum
    float sum = 0.f;
#pragma unroll
    for (int j = 0; j < 8; ++j) {
        const float p = __expf(acc[j] - mx);
        ps[c0 + j] = p;
        sum += p;
    }
    red[tid] = sum; __syncthreads();
    for (int st = 128; st >= 1; st >>= 1) {
        if (tid < st) red[tid] += red[tid + st];
        __syncthreads();
    }
    const float inv = 1.f / red[0];

    // PV: thread (part, d) sums over its 512 keys; coalesced over d
    const int d    = tid & (DHEAD - 1);
    const int part = tid >> 6;            // 0..3
    float oa = 0.f;
    for (int c = part * 512; c < part * 512 + 512; ++c)
        oa = fmaf(ps[c], __half2float(Vp[(size_t)c * DHEAD + d]), oa);
    osum[part][d] = oa;
    __syncthreads();

    if (tid < DHEAD) {
        const float val = (osum[0][tid] + osum[1][tid] + osum[2][tid] + osum[3][tid]) * inv;
        const int b = bh >> 4, h = bh & 15;
        g_att[((size_t)(b * S_LEN)) * D_MODEL + h * DHEAD + tid] = __float2half(val);
    }
}

// ----------------------------------------------------------------------------
extern "C" void kernel_launch(void* const* d_in, const int* in_sizes, int n_in,
                              void* d_out, int out_size)
{
    (void)in_sizes; (void)n_in; (void)out_size;
    const float* x  = (const float*)d_in[0];
    const float* Wq = (const float*)d_in[1];
    const float* bq = (const float*)d_in[2];
    const float* Wk = (const float*)d_in[3];
    const float* bk = (const float*)d_in[4];
    const float* Wv = (const float*)d_in[5];
    const float* bv = (const float*)d_in[6];
    const float* Wo = (const float*)d_in[7];
    const float* bo = (const float*)d_in[8];
    float* out = (float*)d_out;

    __half *xh, *wh, *q, *k, *v, *att;
    cudaGetSymbolAddress((void**)&xh,  g_xh);
    cudaGetSymbolAddress((void**)&wh,  g_wh);
    cudaGetSymbolAddress((void**)&q,   g_q);
    cudaGetSymbolAddress((void**)&k,   g_k);
    cudaGetSymbolAddress((void**)&v,   g_v);
    cudaGetSymbolAddress((void**)&att, g_att);

    cudaFuncSetAttribute(attn_kernel, cudaFuncAttributeMaxDynamicSharedMemorySize, ATT_SMEM);

    splitx_kernel<<<M_TOK * D_MODEL / 1024, 256>>>(x, xh, M_TOK * D_MODEL);
    splitw_kernel<<<dim3(NW / 1024, 4), 256>>>(Wq, Wk, Wv, Wo, wh);

    // fused QKV projections: grid.z = 0/1/2 -> Q/K/V
    gemm_fp16<true><<<dim3(D_MODEL / 128, M_TOK / 128, 3), 256>>>(
        xh, wh, bq, bk, bv, nullptr, q, k, v);

    attn_kernel<<<dim3(S_LEN / 64, BATCH * NHEADS), 128, ATT_SMEM>>>();
    row0_kernel<<<BATCH * NHEADS, 256>>>();   // overwrite global-query rows

    // final projection (Wo is 4th weight in g_wh)
    gemm_fp16<false><<<dim3(D_MODEL / 128, M_TOK / 128), 256>>>(
        att, wh + 3 * (size_t)NW, bo, nullptr, nullptr, out, nullptr, nullptr, nullptr);
}